// round 16
// baseline (speedup 1.0000x reference)
#include <cuda_runtime.h>
#include <math.h>

// ---------------------------------------------------------------------------
// PositionalEdgeGenerator: batch-aware KNN (k=16) + edge-distance MLP
//   output : f32 buffer [ y_nodes[E] | x_nodes[E] | weights[E] ], E = 131072
// R16 = R11 base (34.7us best) + 2 queries per warp (candidate-load reuse).
//   y_subset sorted -> warp's 2 queries ~always share a batch; each stripe's
//   float4 load serves both distance computations (L1 traffic/query halves).
//   Pass1: FULL scan, per-lane top-2 per query -> v_k >= w16_k (tournament
//          drift only raises v). Pass2: recollect od<=v_k per query, ballot-
//   compact (CAP=48). Rank: exact (d2,j) u64 rank == lax.top_k semantics.
//   Guards: nh<16 / nh>48 -> per-query sequential exact fallback.
// ---------------------------------------------------------------------------

#define N_NODES   16384
#define N_SUB     8192
#define N_BATCH   8
#define HIDDEN    128
#define KK        16
#define E_TOTAL   (N_SUB * KK)                // 131072
#define CAP       48                          // hit buffer per query
#define QW        2                           // queries per warp

#define Q_PER_BLOCK  8                        // 4 warps * 2
#define KNN_THREADS  128

// scratch (no allocation allowed)
__device__ float4 g_gx[N_SUB];        // candidate: {px, py, pz, ||px||^2}
__device__ int    g_bstart[N_BATCH + 1];

// ---------------------------------------------------------------------------
__global__ void __launch_bounds__(128) prep_kernel(const float* __restrict__ pos,
                                                   const int* __restrict__ xs)
{
    int j = blockIdx.x * blockDim.x + threadIdx.x;
    if (j >= N_SUB) return;

    int xi = xs[j];
    float p0 = pos[3 * xi + 0];
    float p1 = pos[3 * xi + 1];
    float p2 = pos[3 * xi + 2];
    float xx = __fadd_rn(__fadd_rn(__fmul_rn(p0, p0), __fmul_rn(p1, p1)),
                         __fmul_rn(p2, p2));
    g_gx[j] = make_float4(p0, p1, p2, xx);

    int b  = xi >> 11;                       // batch = node / 2048 (deterministic)
    int bp = (j == 0) ? -1 : (xs[j - 1] >> 11);
    for (int bb = bp + 1; bb <= b; ++bb) g_bstart[bb] = j;
    if (j == N_SUB - 1)
        for (int bb = b + 1; bb <= N_BATCH; ++bb) g_bstart[bb] = N_SUB;
}

// order-preserving f32 -> u32 map (exact R7 form)
__device__ __forceinline__ unsigned int f2ord(float f)
{
    unsigned int u = __float_as_uint(f);
    return (u & 0x80000000u) ? ~u : (u | 0x80000000u);
}

// reference-exact squared distance from a preloaded candidate
__device__ __forceinline__ unsigned int dist_od(float p0, float p1, float p2,
                                                float yy, float4 c)
{
    float dot = __fmaf_rn(p2, c.z, __fmaf_rn(p1, c.y, __fmul_rn(p0, c.x)));
    float d2  = __fsub_rn(__fadd_rn(yy, c.w), __fmul_rn(2.0f, dot));
    return f2ord(d2);
}

// ---------------------------------------------------------------------------
__global__ void __launch_bounds__(KNN_THREADS)
knn_kernel(const float* __restrict__ pos,
           const int* __restrict__ xs,
           const int* __restrict__ ys,
           const float* __restrict__ w1,
           const float* __restrict__ b1,
           const float* __restrict__ w2,
           const float* __restrict__ b2,
           float* __restrict__ out)
{
    __shared__ unsigned long long hitbuf[Q_PER_BLOCK][CAP];   // 3 KB
    __shared__ float sw1[HIDDEN], sb1[HIDDEN], sw2[HIDDEN];

    int tid  = threadIdx.x;
    int warp = tid >> 5;
    int lane = tid & 31;
    int qb   = blockIdx.x * Q_PER_BLOCK + warp * QW;

    sw1[tid] = w1[tid]; sb1[tid] = b1[tid]; sw2[tid] = w2[tid];
    __syncthreads();

    int   yn[QW];  float p0[QW], p1[QW], p2[QW], yy[QW];
    int   qlo[QW], qhi[QW];
#pragma unroll
    for (int k = 0; k < QW; ++k) {
        yn[k] = ys[qb + k];
        p0[k] = pos[3 * yn[k] + 0];
        p1[k] = pos[3 * yn[k] + 1];
        p2[k] = pos[3 * yn[k] + 2];
        yy[k] = __fadd_rn(__fadd_rn(__fmul_rn(p0[k], p0[k]),
                                    __fmul_rn(p1[k], p1[k])),
                          __fmul_rn(p2[k], p2[k]));
        int bb = yn[k] >> 11;
        qlo[k] = g_bstart[bb];
        qhi[k] = g_bstart[bb + 1];
    }
    float bb2 = b2[0];

    int lo = min(qlo[0], qlo[1]);            // union range (equal ~always)
    int hi = max(qhi[0], qhi[1]);
    int nt = (hi - lo + 31) >> 5;            // warp-uniform trip count

    // ---------- pass 1: shared load, per-query per-lane top-2 ----------
    unsigned int a0[QW], a1[QW];
#pragma unroll
    for (int k = 0; k < QW; ++k) { a0[k] = 0xFFFFFFFFu; a1[k] = 0xFFFFFFFFu; }

#pragma unroll 2
    for (int t = 0; t < nt; ++t) {
        int j = lo + t * 32 + lane;
        bool valid = j < hi;
        float4 c = make_float4(0.f, 0.f, 0.f, 0.f);
        if (valid) c = g_gx[j];              // ONE load serves both queries
#pragma unroll
        for (int k = 0; k < QW; ++k) {
            bool in = valid && (j >= qlo[k]) && (j < qhi[k]);
            unsigned int od = in ? dist_od(p0[k], p1[k], p2[k], yy[k], c)
                                 : 0xFFFFFFFFu;
            unsigned int mx = umax(od, a0[k]);
            a0[k] = umin(od, a0[k]);
            a1[k] = umin(a1[k], mx);
        }
    }

    // ---------- tournament per query: v_k = 16th smallest of 64 ----------
    unsigned int v[QW];
#pragma unroll
    for (int k = 0; k < QW; ++k) {
        unsigned int vv = 0xFFFFFFFFu;
        int h = 0;
        unsigned int cur = a0[k];
#pragma unroll
        for (int r = 0; r < KK; ++r) {
            unsigned int m = cur;
#pragma unroll
            for (int d = 1; d < 32; d <<= 1)
                m = umin(m, __shfl_xor_sync(0xFFFFFFFFu, m, d));
            vv = m;
            if (cur == m) { ++h; cur = (h == 1) ? a1[k] : 0xFFFFFFFFu; }
        }
        v[k] = vv;
    }

    // ---------- pass 2: shared load, per-query ballot-compact ----------
    int nh[QW];
#pragma unroll
    for (int k = 0; k < QW; ++k) nh[k] = 0;

    for (int t = 0; t < nt; ++t) {
        int j = lo + t * 32 + lane;
        bool valid = j < hi;
        float4 c = make_float4(0.f, 0.f, 0.f, 0.f);
        if (valid) c = g_gx[j];
#pragma unroll
        for (int k = 0; k < QW; ++k) {
            bool in = valid && (j >= qlo[k]) && (j < qhi[k]);
            unsigned int od = in ? dist_od(p0[k], p1[k], p2[k], yy[k], c)
                                 : 0xFFFFFFFFu;
            bool hit = in && (od <= v[k]);
            unsigned int mask = __ballot_sync(0xFFFFFFFFu, hit);
            int off = __popc(mask & ((1u << lane) - 1u));
            if (hit && (nh[k] + off) < CAP)
                hitbuf[warp * QW + k][nh[k] + off] =
                    ((unsigned long long)od << 32) | (unsigned int)j;
            nh[k] += __popc(mask);
        }
    }
    __syncwarp();

    // ---------- per-query rank + MLP epilogue (or exact fallback) ----------
#pragma unroll
    for (int k = 0; k < QW; ++k) {
        int q = qb + k;
        if (nh[k] >= KK && nh[k] <= CAP) {
            for (int i = lane; i < nh[k]; i += 32) {
                unsigned long long ki = hitbuf[warp * QW + k][i];
                int rank = 0;
                for (int m = 0; m < nh[k]; ++m)
                    rank += (hitbuf[warp * QW + k][m] < ki) ? 1 : 0;
                if (rank < KK) {
                    int jj = (int)(ki & 0xFFFFFFFFull);
                    int e  = q * KK + rank;
                    int xn = xs[jj];
                    out[e]           = (float)yn[k];
                    out[E_TOTAL + e] = (float)xn;

                    float4 c = g_gx[jj];
                    float d0  = __fsub_rn(p0[k], c.x);
                    float d1  = __fsub_rn(p1[k], c.y);
                    float d2_ = __fsub_rn(p2[k], c.z);
                    float s2  = __fadd_rn(__fadd_rn(__fmul_rn(d0, d0),
                                                    __fmul_rn(d1, d1)),
                                          __fmul_rn(d2_, d2_));
                    float nd  = __fsqrt_rn(s2);

                    float acc = 0.0f;
#pragma unroll 8
                    for (int i2 = 0; i2 < HIDDEN; ++i2) {
                        float hh = __fadd_rn(__fmul_rn(nd, sw1[i2]), sb1[i2]);
                        hh = fmaxf(hh, 0.0f);
                        acc = __fmaf_rn(hh, sw2[i2], acc);
                    }
                    out[2 * E_TOTAL + e] = fmaxf(__fadd_rn(acc, bb2), 0.0f);
                }
            }
        } else {
            // exact sequential fallback over this query's own range (~never)
            int ntk = (qhi[k] - qlo[k] + 31) >> 5;
            unsigned long long last = 0ull;
            for (int r = 0; r < KK; ++r) {
                unsigned long long best = ~0ull;
                for (int t = 0; t < ntk; ++t) {
                    int j = qlo[k] + t * 32 + lane;
                    if (j < qhi[k]) {
                        float4 c = g_gx[j];
                        unsigned int od = dist_od(p0[k], p1[k], p2[k], yy[k], c);
                        unsigned long long key =
                            ((unsigned long long)od << 32) | (unsigned int)j;
                        if (key > last && key < best) best = key;
                    }
                }
#pragma unroll
                for (int d = 1; d < 32; d <<= 1) {
                    unsigned long long o = __shfl_xor_sync(0xFFFFFFFFu, best, d);
                    best = (o < best) ? o : best;
                }
                if (lane == 0) {
                    int jj = (int)(best & 0xFFFFFFFFull);
                    int e  = q * KK + r;
                    int xn = xs[jj];
                    out[e]           = (float)yn[k];
                    out[E_TOTAL + e] = (float)xn;

                    float4 c = g_gx[jj];
                    float d0  = __fsub_rn(p0[k], c.x);
                    float d1  = __fsub_rn(p1[k], c.y);
                    float d2_ = __fsub_rn(p2[k], c.z);
                    float s2  = __fadd_rn(__fadd_rn(__fmul_rn(d0, d0),
                                                    __fmul_rn(d1, d1)),
                                          __fmul_rn(d2_, d2_));
                    float nd  = __fsqrt_rn(s2);

                    float acc = 0.0f;
                    for (int i2 = 0; i2 < HIDDEN; ++i2) {
                        float hh = __fadd_rn(__fmul_rn(nd, sw1[i2]), sb1[i2]);
                        hh = fmaxf(hh, 0.0f);
                        acc = __fmaf_rn(hh, sw2[i2], acc);
                    }
                    out[2 * E_TOTAL + e] = fmaxf(__fadd_rn(acc, bb2), 0.0f);
                }
                last = best;
            }
        }
    }
}

// ---------------------------------------------------------------------------
extern "C" void kernel_launch(void* const* d_in, const int* in_sizes, int n_in,
                              void* d_out, int out_size)
{
    (void)in_sizes; (void)out_size;
    const float* pos = (const float*)d_in[0];
    const int*   xs  = (const int*)d_in[1];
    const int*   ys  = (const int*)d_in[2];
    const float* w1 = (const float*)d_in[n_in - 4];
    const float* b1 = (const float*)d_in[n_in - 3];
    const float* w2 = (const float*)d_in[n_in - 2];
    const float* b2 = (const float*)d_in[n_in - 1];
    float* out = (float*)d_out;

    prep_kernel<<<N_SUB / 128, 128>>>(pos, xs);
    knn_kernel<<<N_SUB / Q_PER_BLOCK, KNN_THREADS>>>(pos, xs, ys,
                                                     w1, b1, w2, b2, out);
}

// round 17
// speedup vs baseline: 1.2235x; 1.2235x over previous
#include <cuda_runtime.h>
#include <math.h>

// ---------------------------------------------------------------------------
// PositionalEdgeGenerator: batch-aware KNN (k=16) + edge-distance MLP
//   output : f32 buffer [ y_nodes[E] | x_nodes[E] | weights[E] ], E = 131072
// R17 = R11 verbatim (34.7us best, rel_err 0.0) + two latency micro-opts:
//   (1) __launch_bounds__(128,12): cap regs ~42 -> 12 blocks/SM, smaller tail
//   (2) #pragma unroll 4 on both scan loops: 4 LDGs in flight per lane
//   Pass1: per-lane top-2 (u32 ordered d2), FULL scan -> tournament v >= w16.
//   Pass2: recollect od <= v, ballot-compact (CAP=48).
//   Rank: exact (d2,j) u64 rank == lax.top_k. Guards -> exact fallback.
// ---------------------------------------------------------------------------

#define N_NODES   16384
#define N_SUB     8192
#define N_BATCH   8
#define HIDDEN    128
#define KK        16
#define E_TOTAL   (N_SUB * KK)                // 131072
#define CAP       48                          // hit buffer per warp

#define Q_PER_BLOCK  4
#define KNN_THREADS  (32 * Q_PER_BLOCK)       // 128

// scratch (no allocation allowed)
__device__ float4 g_gx[N_SUB];        // candidate: {px, py, pz, ||px||^2}
__device__ int    g_bstart[N_BATCH + 1];

// ---------------------------------------------------------------------------
__global__ void __launch_bounds__(128) prep_kernel(const float* __restrict__ pos,
                                                   const int* __restrict__ xs)
{
    int j = blockIdx.x * blockDim.x + threadIdx.x;
    if (j >= N_SUB) return;

    int xi = xs[j];
    float p0 = pos[3 * xi + 0];
    float p1 = pos[3 * xi + 1];
    float p2 = pos[3 * xi + 2];
    float xx = __fadd_rn(__fadd_rn(__fmul_rn(p0, p0), __fmul_rn(p1, p1)),
                         __fmul_rn(p2, p2));
    g_gx[j] = make_float4(p0, p1, p2, xx);

    int b  = xi >> 11;                       // batch = node / 2048 (deterministic)
    int bp = (j == 0) ? -1 : (xs[j - 1] >> 11);
    for (int bb = bp + 1; bb <= b; ++bb) g_bstart[bb] = j;
    if (j == N_SUB - 1)
        for (int bb = b + 1; bb <= N_BATCH; ++bb) g_bstart[bb] = N_SUB;
}

// order-preserving f32 -> u32 map (exact R7 form)
__device__ __forceinline__ unsigned int f2ord(float f)
{
    unsigned int u = __float_as_uint(f);
    return (u & 0x80000000u) ? ~u : (u | 0x80000000u);
}

// reference-exact squared distance, ordered
__device__ __forceinline__ unsigned int cand_od(float p0, float p1, float p2,
                                                float yy, int j)
{
    float4 c  = g_gx[j];
    float dot = __fmaf_rn(p2, c.z, __fmaf_rn(p1, c.y, __fmul_rn(p0, c.x)));
    float d2  = __fsub_rn(__fadd_rn(yy, c.w), __fmul_rn(2.0f, dot));
    return f2ord(d2);
}

// ---------------------------------------------------------------------------
__global__ void __launch_bounds__(KNN_THREADS, 12)
knn_kernel(const float* __restrict__ pos,
           const int* __restrict__ xs,
           const int* __restrict__ ys,
           const float* __restrict__ w1,
           const float* __restrict__ b1,
           const float* __restrict__ w2,
           const float* __restrict__ b2,
           float* __restrict__ out)
{
    __shared__ unsigned long long hitbuf[Q_PER_BLOCK][CAP];
    __shared__ float sw1[HIDDEN], sb1[HIDDEN], sw2[HIDDEN];

    int tid  = threadIdx.x;
    int warp = tid >> 5;
    int lane = tid & 31;
    int q    = blockIdx.x * Q_PER_BLOCK + warp;

    sw1[tid] = w1[tid]; sb1[tid] = b1[tid]; sw2[tid] = w2[tid];
    __syncthreads();

    int yn = ys[q];
    float p0 = pos[3 * yn + 0];
    float p1 = pos[3 * yn + 1];
    float p2 = pos[3 * yn + 2];
    float yy = __fadd_rn(__fadd_rn(__fmul_rn(p0, p0), __fmul_rn(p1, p1)),
                         __fmul_rn(p2, p2));
    float bb2 = b2[0];

    int b  = yn >> 11;
    int lo = g_bstart[b];
    int hi = g_bstart[b + 1];
    int nt = (hi - lo + 31) >> 5;            // warp-uniform trip count

    // ---------- pass 1: per-lane top-2 of ordered d2 (FULL scan) ----------
    unsigned int a0 = 0xFFFFFFFFu, a1 = 0xFFFFFFFFu;      // a0 <= a1
#pragma unroll 4
    for (int t = 0; t < nt; ++t) {
        int j = lo + t * 32 + lane;
        unsigned int od = 0xFFFFFFFFu;
        if (j < hi) od = cand_od(p0, p1, p2, yy, j);
        unsigned int mx = umax(od, a0);
        a0 = umin(od, a0);
        a1 = umin(a1, mx);
    }

    // ---------- tournament: v = 16th smallest of the 64 values ----------
    // ties double-consume -> v only grows: still an upper bound on true w16
    unsigned int v = 0xFFFFFFFFu;
    int h = 0;
    unsigned int cur = a0;
#pragma unroll
    for (int r = 0; r < KK; ++r) {
        unsigned int m = cur;
#pragma unroll
        for (int d = 1; d < 32; d <<= 1)
            m = umin(m, __shfl_xor_sync(0xFFFFFFFFu, m, d));
        v = m;
        if (cur == m) { ++h; cur = (h == 1) ? a1 : 0xFFFFFFFFu; }
    }

    // ---------- pass 2: recollect all hits (od <= v), ballot-compact ----------
    int nh = 0;
#pragma unroll 4
    for (int t = 0; t < nt; ++t) {
        int j = lo + t * 32 + lane;
        bool valid = j < hi;
        unsigned int od = 0xFFFFFFFFu;
        if (valid) od = cand_od(p0, p1, p2, yy, j);
        bool hit = valid && (od <= v);
        unsigned int mask = __ballot_sync(0xFFFFFFFFu, hit);
        int off = __popc(mask & ((1u << lane) - 1u));
        if (hit && (nh + off) < CAP)
            hitbuf[warp][nh + off] =
                ((unsigned long long)od << 32) | (unsigned int)j;
        nh += __popc(mask);
    }
    __syncwarp();

    if (nh >= KK && nh <= CAP) {
        // ---------- exact rank over hits; emit ranks 0..15 ----------
        for (int i = lane; i < nh; i += 32) {
            unsigned long long ki = hitbuf[warp][i];
            int rank = 0;
            for (int m = 0; m < nh; ++m)
                rank += (hitbuf[warp][m] < ki) ? 1 : 0;
            if (rank < KK) {
                int jj = (int)(ki & 0xFFFFFFFFull);
                int e  = q * KK + rank;
                int xn = xs[jj];
                out[e]           = (float)yn;
                out[E_TOTAL + e] = (float)xn;

                float4 c = g_gx[jj];
                float d0  = __fsub_rn(p0, c.x);
                float d1  = __fsub_rn(p1, c.y);
                float d2_ = __fsub_rn(p2, c.z);
                float s2  = __fadd_rn(__fadd_rn(__fmul_rn(d0, d0),
                                                __fmul_rn(d1, d1)),
                                      __fmul_rn(d2_, d2_));
                float nd  = __fsqrt_rn(s2);

                float acc = 0.0f;
#pragma unroll 8
                for (int i2 = 0; i2 < HIDDEN; ++i2) {
                    float hh = __fadd_rn(__fmul_rn(nd, sw1[i2]), sb1[i2]);
                    hh = fmaxf(hh, 0.0f);
                    acc = __fmaf_rn(hh, sw2[i2], acc);
                }
                out[2 * E_TOTAL + e] = fmaxf(__fadd_rn(acc, bb2), 0.0f);
            }
        }
    } else {
        // ---------- exact sequential fallback (warp-uniform; ~never) ----------
        unsigned long long last = 0ull;
        for (int r = 0; r < KK; ++r) {
            unsigned long long best = ~0ull;
            for (int t = 0; t < nt; ++t) {
                int j = lo + t * 32 + lane;
                if (j < hi) {
                    unsigned int od = cand_od(p0, p1, p2, yy, j);
                    unsigned long long key =
                        ((unsigned long long)od << 32) | (unsigned int)j;
                    if (key > last && key < best) best = key;
                }
            }
#pragma unroll
            for (int d = 1; d < 32; d <<= 1) {
                unsigned long long o = __shfl_xor_sync(0xFFFFFFFFu, best, d);
                best = (o < best) ? o : best;
            }
            if (lane == 0) {
                int jj = (int)(best & 0xFFFFFFFFull);
                int e  = q * KK + r;
                int xn = xs[jj];
                out[e]           = (float)yn;
                out[E_TOTAL + e] = (float)xn;

                float4 c = g_gx[jj];
                float d0  = __fsub_rn(p0, c.x);
                float d1  = __fsub_rn(p1, c.y);
                float d2_ = __fsub_rn(p2, c.z);
                float s2  = __fadd_rn(__fadd_rn(__fmul_rn(d0, d0),
                                                __fmul_rn(d1, d1)),
                                      __fmul_rn(d2_, d2_));
                float nd  = __fsqrt_rn(s2);

                float acc = 0.0f;
                for (int i2 = 0; i2 < HIDDEN; ++i2) {
                    float hh = __fadd_rn(__fmul_rn(nd, sw1[i2]), sb1[i2]);
                    hh = fmaxf(hh, 0.0f);
                    acc = __fmaf_rn(hh, sw2[i2], acc);
                }
                out[2 * E_TOTAL + e] = fmaxf(__fadd_rn(acc, bb2), 0.0f);
            }
            last = best;
        }
    }
}

// ---------------------------------------------------------------------------
extern "C" void kernel_launch(void* const* d_in, const int* in_sizes, int n_in,
                              void* d_out, int out_size)
{
    (void)in_sizes; (void)out_size;
    const float* pos = (const float*)d_in[0];
    const int*   xs  = (const int*)d_in[1];
    const int*   ys  = (const int*)d_in[2];
    const float* w1 = (const float*)d_in[n_in - 4];
    const float* b1 = (const float*)d_in[n_in - 3];
    const float* w2 = (const float*)d_in[n_in - 2];
    const float* b2 = (const float*)d_in[n_in - 1];
    float* out = (float*)d_out;

    prep_kernel<<<N_SUB / 128, 128>>>(pos, xs);
    knn_kernel<<<N_SUB / Q_PER_BLOCK, KNN_THREADS>>>(pos, xs, ys,
                                                     w1, b1, w2, b2, out);
}